// round 2
// baseline (speedup 1.0000x reference)
#include <cuda_runtime.h>
#include <cuda_bf16.h>
#include <cstdint>

// Problem constants
#define NROWS_TOTAL 4096   // B*T
#define SEQ 32             // inner sequence length S
#define EDIM 256           // embed
#define HDIM 256           // hidden
#define GDIM 1024          // 4*H
#define ROWS 32            // rows per CTA
#define NCTAS 128          // 4096/32
#define NTHREADS 256

// smem strides (floats), padded for bank-conflict avoidance
#define GS 1025            // gates row stride
#define XS 260             // Xs row stride
#define HS 260             // Hs row stride
#define CS 257             // Cs row stride
#define SMEM_FLOATS (ROWS*(GS+XS+HS+CS))
#define SMEM_BYTES (SMEM_FLOATS*4)   // 230,656 <= 232,448 opt-in limit

// Pre-rounded (tf32) weights + fused bias scratch
__device__ float g_wih[GDIM*EDIM];
__device__ float g_whh[GDIM*HDIM];
__device__ float g_bsum[GDIM];

__device__ __forceinline__ float tf32_round_f(float x) {
    float r;
    asm("cvt.rna.tf32.f32 %0, %1;" : "=f"(r) : "f"(x));
    return r;
}
__device__ __forceinline__ uint32_t tf32_round_u(float x) {
    uint32_t r;
    asm("cvt.rna.tf32.f32 %0, %1;" : "=r"(r) : "f"(x));
    return r;
}

#define MMA_TF32(d, a, b0, b1)                                              \
    asm volatile("mma.sync.aligned.m16n8k8.row.col.f32.tf32.tf32.f32 "      \
                 "{%0,%1,%2,%3}, {%4,%5,%6,%7}, {%8,%9}, {%0,%1,%2,%3};"    \
                 : "+f"((d)[0]), "+f"((d)[1]), "+f"((d)[2]), "+f"((d)[3])   \
                 : "r"((a)[0]), "r"((a)[1]), "r"((a)[2]), "r"((a)[3]),      \
                   "r"(b0), "r"(b1))

__global__ void prep_kernel(const float* __restrict__ wih,
                            const float* __restrict__ whh,
                            const float* __restrict__ bih,
                            const float* __restrict__ bhh) {
    int i = blockIdx.x * blockDim.x + threadIdx.x;
    if (i < GDIM*EDIM) {
        g_wih[i] = tf32_round_f(wih[i]);
        g_whh[i] = tf32_round_f(whh[i]);
    }
    if (i < GDIM) g_bsum[i] = bih[i] + bhh[i];
}

__device__ __forceinline__ float sigmoidf_(float x) {
    return 1.0f / (1.0f + __expf(-x));
}

__global__ __launch_bounds__(NTHREADS, 1)
void lstm_fused_kernel(const float* __restrict__ x, float* __restrict__ out) {
    extern __shared__ float sm[];
    float* gates = sm;                    // [32][GS]
    float* Xs    = gates + ROWS*GS;       // [32][XS] tf32-rounded
    float* Hs    = Xs    + ROWS*XS;       // [32][HS] fp32
    float* Cs    = Hs    + ROWS*HS;       // [32][CS] fp32

    const int tid  = threadIdx.x;
    const int lane = tid & 31;
    const int w    = tid >> 5;            // warp id 0..7
    const int grp  = lane >> 2;           // 0..7
    const int tg   = lane & 3;            // 0..3
    const long rowbase = (long)blockIdx.x * ROWS;

    // zero h, c state
    for (int i = tid; i < ROWS*HS; i += NTHREADS) Hs[i] = 0.0f;
    for (int i = tid; i < ROWS*CS; i += NTHREADS) Cs[i] = 0.0f;
    __syncthreads();

    const float* xbase = x + rowbase * (SEQ*EDIM);

    for (int s = 0; s < SEQ; ++s) {
        // ---- load x_s tile [32][256], tf32-rounded, into Xs ----
        {
            const long srow = (long)s * EDIM;
            #pragma unroll
            for (int it = 0; it < 8; ++it) {
                int fi = tid + it * NTHREADS;    // 0..2047 (float4 index)
                int r  = fi >> 6;                // 64 float4 per row
                int cq = fi & 63;
                const float4 v = *((const float4*)(xbase + (long)r*(SEQ*EDIM) + srow) + cq);
                float* dst = &Xs[r*XS + cq*4];
                dst[0] = tf32_round_f(v.x);
                dst[1] = tf32_round_f(v.y);
                dst[2] = tf32_round_f(v.z);
                dst[3] = tf32_round_f(v.w);
            }
        }
        __syncthreads();

        // ---- GEMM: gates[32][1024] = Xs@Wih^T + Hs@Whh^T + bsum ----
        const bool doH = (s > 0);
        #pragma unroll
        for (int nc = 0; nc < 2; ++nc) {
            const int nbase = w * 128 + nc * 64;
            float d[2][8][4];
            #pragma unroll
            for (int nf = 0; nf < 8; ++nf) {
                int col = nbase + nf*8 + 2*tg;
                float b0v = g_bsum[col], b1v = g_bsum[col + 1];
                d[0][nf][0] = b0v; d[0][nf][1] = b1v; d[0][nf][2] = b0v; d[0][nf][3] = b1v;
                d[1][nf][0] = b0v; d[1][nf][1] = b1v; d[1][nf][2] = b0v; d[1][nf][3] = b1v;
            }

            // X part: K = 0..255 (Xs already tf32)
            {
                const uint32_t* A = (const uint32_t*)Xs;
                const uint32_t* W = (const uint32_t*)g_wih;
                #pragma unroll 4
                for (int kb = 0; kb < EDIM; kb += 8) {
                    uint32_t a[2][4];
                    #pragma unroll
                    for (int mh = 0; mh < 2; ++mh) {
                        int r0 = mh*16 + grp;
                        a[mh][0] = A[r0*XS + kb + tg];
                        a[mh][1] = A[(r0+8)*XS + kb + tg];
                        a[mh][2] = A[r0*XS + kb + 4 + tg];
                        a[mh][3] = A[(r0+8)*XS + kb + 4 + tg];
                    }
                    #pragma unroll
                    for (int nf = 0; nf < 8; ++nf) {
                        const uint32_t* wr = W + (long)(nbase + nf*8 + grp)*EDIM + kb + tg;
                        uint32_t b0 = wr[0], b1 = wr[4];
                        MMA_TF32(d[0][nf], a[0], b0, b1);
                        MMA_TF32(d[1][nf], a[1], b0, b1);
                    }
                }
            }
            // H part: K = 256..511 (round h to tf32 on the fly)
            if (doH) {
                const uint32_t* W = (const uint32_t*)g_whh;
                #pragma unroll 4
                for (int kb = 0; kb < HDIM; kb += 8) {
                    uint32_t a[2][4];
                    #pragma unroll
                    for (int mh = 0; mh < 2; ++mh) {
                        int r0 = mh*16 + grp;
                        a[mh][0] = tf32_round_u(Hs[r0*HS + kb + tg]);
                        a[mh][1] = tf32_round_u(Hs[(r0+8)*HS + kb + tg]);
                        a[mh][2] = tf32_round_u(Hs[r0*HS + kb + 4 + tg]);
                        a[mh][3] = tf32_round_u(Hs[(r0+8)*HS + kb + 4 + tg]);
                    }
                    #pragma unroll
                    for (int nf = 0; nf < 8; ++nf) {
                        const uint32_t* wr = W + (long)(nbase + nf*8 + grp)*HDIM + kb + tg;
                        uint32_t b0 = wr[0], b1 = wr[4];
                        MMA_TF32(d[0][nf], a[0], b0, b1);
                        MMA_TF32(d[1][nf], a[1], b0, b1);
                    }
                }
            }
            // store gate slice to smem
            #pragma unroll
            for (int nf = 0; nf < 8; ++nf) {
                int col = nbase + nf*8 + 2*tg;
                #pragma unroll
                for (int mh = 0; mh < 2; ++mh) {
                    int r0 = mh*16 + grp;
                    gates[r0*GS + col]         = d[mh][nf][0];
                    gates[r0*GS + col + 1]     = d[mh][nf][1];
                    gates[(r0+8)*GS + col]     = d[mh][nf][2];
                    gates[(r0+8)*GS + col + 1] = d[mh][nf][3];
                }
            }
        }
        __syncthreads();

        // ---- activation / state update: row = lane, units w*32..w*32+31 ----
        {
            const int r = lane;
            const float* grow = &gates[r*GS];
            #pragma unroll 4
            for (int jj = 0; jj < 32; ++jj) {
                int u = w*32 + jj;
                float gi = grow[u];
                float gf = grow[256 + u];
                float gg = grow[512 + u];
                float go = grow[768 + u];
                float iv = sigmoidf_(gi);
                float fv = sigmoidf_(gf);
                float gv = tanhf(gg);
                float ov = sigmoidf_(go);
                float c  = fv * Cs[r*CS + u] + iv * gv;
                Cs[r*CS + u] = c;
                float h  = ov * tanhf(c);
                Hs[r*HS + u] = h;
                if (s == SEQ - 1) out[(rowbase + r)*HDIM + u] = h;
            }
        }
        __syncthreads();
    }
}

extern "C" void kernel_launch(void* const* d_in, const int* in_sizes, int n_in,
                              void* d_out, int out_size) {
    const float* x   = (const float*)d_in[0];
    const float* wih = (const float*)d_in[1];
    const float* whh = (const float*)d_in[2];
    const float* bih = (const float*)d_in[3];
    const float* bhh = (const float*)d_in[4];
    float* out = (float*)d_out;

    cudaFuncSetAttribute(lstm_fused_kernel,
                         cudaFuncAttributeMaxDynamicSharedMemorySize, SMEM_BYTES);

    prep_kernel<<<(GDIM*EDIM + 255)/256, 256>>>(wih, whh, bih, bhh);
    lstm_fused_kernel<<<NCTAS, NTHREADS, SMEM_BYTES>>>(x, out);
}

// round 3
// speedup vs baseline: 2.8085x; 2.8085x over previous
#include <cuda_runtime.h>
#include <cuda_bf16.h>
#include <cstdint>

#define SEQ 32
#define EDIM 256
#define HDIM 256
#define GDIM 1024
#define ROWS 32
#define NCTAS 128
#define NTHREADS 256

#define XS 260   // Xs row stride (floats): conflict-free for (4*grp+tg) lane pattern
#define HS 260
#define SMEM_FLOATS (ROWS*XS + 2*ROWS*HS)
#define SMEM_BYTES (SMEM_FLOATS*4)   // 99,840 B

// Packed tf32 weights in per-lane MMA B-fragment order:
// index = ((((wb*2 + nc)*64 + kb)*8 + nf)*32 + lane), kb 0..31 = X part, 32..63 = H part
__device__ uint2 g_wpk[8*2*64*8*32];
__device__ float g_bperm[GDIM];   // bias in gate-interleaved (permuted) column space

__device__ __forceinline__ float tf32_round_f(float x) {
    float r;
    asm("cvt.rna.tf32.f32 %0, %1;" : "=f"(r) : "f"(x));
    return r;
}
__device__ __forceinline__ uint32_t tf32_round_u(float x) {
    uint32_t r;
    asm("cvt.rna.tf32.f32 %0, %1;" : "=r"(r) : "f"(x));
    return r;
}

#define MMA_TF32(d, a, b0, b1)                                              \
    asm volatile("mma.sync.aligned.m16n8k8.row.col.f32.tf32.tf32.f32 "      \
                 "{%0,%1,%2,%3}, {%4,%5,%6,%7}, {%8,%9}, {%0,%1,%2,%3};"    \
                 : "+f"((d)[0]), "+f"((d)[1]), "+f"((d)[2]), "+f"((d)[3])   \
                 : "r"((a)[0]), "r"((a)[1]), "r"((a)[2]), "r"((a)[3]),      \
                   "r"(b0), "r"(b1))

// Prep: gate-interleave permutation + tf32 rounding + fragment packing.
// Permuted col p: unit u = p>>2, gate g = p&3, original W row = g*256 + u.
__global__ void prep_kernel(const float* __restrict__ wih,
                            const float* __restrict__ whh,
                            const float* __restrict__ bih,
                            const float* __restrict__ bhh) {
    int i = blockIdx.x * blockDim.x + threadIdx.x;   // 0..262143
    if (i >= 8*2*64*8*32) return;
    int lane = i & 31;
    int nf   = (i >> 5) & 7;
    int kb   = (i >> 8) & 63;
    int nc   = (i >> 14) & 1;
    int wb   = i >> 15;
    int grp  = lane >> 2;
    int tg   = lane & 3;

    int colperm = wb*128 + nc*64 + nf*8 + grp;
    int unit = colperm >> 2;
    int gate = colperm & 3;
    int orow = gate*256 + unit;
    int kk   = (kb & 31)*8 + tg;
    const float* W = (kb < 32) ? wih : whh;

    uint2 v;
    v.x = tf32_round_u(W[orow*256 + kk]);
    v.y = tf32_round_u(W[orow*256 + kk + 4]);
    g_wpk[i] = v;

    if (i < GDIM) {
        int u2 = i >> 2, g2 = i & 3;
        g_bperm[i] = bih[g2*256 + u2] + bhh[g2*256 + u2];
    }
}

__device__ __forceinline__ float sigmoidf_(float x) {
    return 1.0f / (1.0f + __expf(-x));
}

__global__ __launch_bounds__(NTHREADS, 1)
void lstm_fused_kernel(const float* __restrict__ x, float* __restrict__ out) {
    extern __shared__ float sm[];
    float* Xs = sm;               // [32][XS], tf32-rounded x_s tile
    float* Hb = Xs + ROWS*XS;     // two ping-pong h buffers [32][HS], tf32-rounded

    const int tid  = threadIdx.x;
    const int lane = tid & 31;
    const int w    = tid >> 5;
    const int grp  = lane >> 2;
    const int tg   = lane & 3;
    const int tgl  = tg & 1;
    const int tgh  = tg >> 1;
    const long rowbase = (long)blockIdx.x * ROWS;

    // c-state in registers: [nc][mh][nf]
    float cst[2][2][8];
    #pragma unroll
    for (int a = 0; a < 2; ++a)
        #pragma unroll
        for (int b = 0; b < 2; ++b)
            #pragma unroll
            for (int c = 0; c < 8; ++c) cst[a][b][c] = 0.0f;

    const float* xbase = x + rowbase * (SEQ*EDIM);

    for (int s = 0; s < SEQ; ++s) {
        // ---- stage x_s tile [32][256] (tf32-rounded) ----
        {
            const long srow = (long)s * EDIM;
            #pragma unroll
            for (int it = 0; it < 8; ++it) {
                int fi = tid + it * NTHREADS;
                int r  = fi >> 6;
                int cq = fi & 63;
                const float4 v = *((const float4*)(xbase + (long)r*(SEQ*EDIM) + srow) + cq);
                float* dst = &Xs[r*XS + cq*4];
                dst[0] = tf32_round_f(v.x);
                dst[1] = tf32_round_f(v.y);
                dst[2] = tf32_round_f(v.z);
                dst[3] = tf32_round_f(v.w);
            }
        }
        __syncthreads();

        const float* Hcur = Hb + (s & 1) * ROWS*HS;
        float*       Hnxt = Hb + ((s + 1) & 1) * ROWS*HS;
        const bool doH = (s > 0);

        #pragma unroll
        for (int nc = 0; nc < 2; ++nc) {
            const int nbase = w*128 + nc*64;
            const int ubase = (nbase >> 2);             // units for this slice
            float d[2][8][4];
            #pragma unroll
            for (int nf = 0; nf < 8; ++nf) {
                int col = nbase + nf*8 + 2*tg;
                float b0v = g_bperm[col], b1v = g_bperm[col + 1];
                d[0][nf][0] = b0v; d[0][nf][1] = b1v; d[0][nf][2] = b0v; d[0][nf][3] = b1v;
                d[1][nf][0] = b0v; d[1][nf][1] = b1v; d[1][nf][2] = b0v; d[1][nf][3] = b1v;
            }

            const uint2* wp = g_wpk + ((long)(w*2 + nc) * 64 * 8) * 32 + lane;

            // X part: K = 0..255
            {
                const uint32_t* A = (const uint32_t*)Xs;
                #pragma unroll 4
                for (int kb = 0; kb < 32; ++kb) {
                    const int k8 = kb*8;
                    uint32_t a[2][4];
                    #pragma unroll
                    for (int mh = 0; mh < 2; ++mh) {
                        int r0 = mh*16 + grp;
                        a[mh][0] = A[r0*XS + k8 + tg];
                        a[mh][1] = A[(r0+8)*XS + k8 + tg];
                        a[mh][2] = A[r0*XS + k8 + 4 + tg];
                        a[mh][3] = A[(r0+8)*XS + k8 + 4 + tg];
                    }
                    #pragma unroll
                    for (int nf = 0; nf < 8; ++nf) {
                        uint2 b = wp[(kb*8 + nf)*32];
                        MMA_TF32(d[0][nf], a[0], b.x, b.y);
                        MMA_TF32(d[1][nf], a[1], b.x, b.y);
                    }
                }
            }
            // H part: K = 256..511 (Hcur already tf32-rounded)
            if (doH) {
                const uint32_t* A = (const uint32_t*)Hcur;
                #pragma unroll 4
                for (int kb = 0; kb < 32; ++kb) {
                    const int k8 = kb*8;
                    uint32_t a[2][4];
                    #pragma unroll
                    for (int mh = 0; mh < 2; ++mh) {
                        int r0 = mh*16 + grp;
                        a[mh][0] = A[r0*HS + k8 + tg];
                        a[mh][1] = A[(r0+8)*HS + k8 + tg];
                        a[mh][2] = A[r0*HS + k8 + 4 + tg];
                        a[mh][3] = A[(r0+8)*HS + k8 + 4 + tg];
                    }
                    #pragma unroll
                    for (int nf = 0; nf < 8; ++nf) {
                        uint2 b = wp[((32 + kb)*8 + nf)*32];
                        MMA_TF32(d[0][nf], a[0], b.x, b.y);
                        MMA_TF32(d[1][nf], a[1], b.x, b.y);
                    }
                }
            }

            // ---- activation in registers ----
            // even tg-lane handles row grp+16mh; odd tg-lane handles row grp+8+16mh.
            #pragma unroll
            for (int mh = 0; mh < 2; ++mh) {
                #pragma unroll
                for (int nf = 0; nf < 8; ++nf) {
                    float c0 = d[mh][nf][0], c1 = d[mh][nf][1];
                    float c2 = d[mh][nf][2], c3 = d[mh][nf][3];
                    float x0 = __shfl_xor_sync(0xffffffffu, tgl ? c0 : c2, 1);
                    float x1 = __shfl_xor_sync(0xffffffffu, tgl ? c1 : c3, 1);
                    float gi = tgl ? x0 : c0;
                    float gf = tgl ? x1 : c1;
                    float gg = tgl ? c2 : x0;
                    float go = tgl ? c3 : x1;
                    int row  = grp + 8*tgl + 16*mh;
                    int u    = ubase + 2*nf + tgh;
                    float cv = sigmoidf_(gf) * cst[nc][mh][nf]
                             + sigmoidf_(gi) * tanhf(gg);
                    cst[nc][mh][nf] = cv;
                    float h = sigmoidf_(go) * tanhf(cv);
                    Hnxt[row*HS + u] = tf32_round_f(h);
                    if (s == SEQ - 1) out[(rowbase + row)*HDIM + u] = h;
                }
            }
        }
        __syncthreads();
    }
}

extern "C" void kernel_launch(void* const* d_in, const int* in_sizes, int n_in,
                              void* d_out, int out_size) {
    const float* x   = (const float*)d_in[0];
    const float* wih = (const float*)d_in[1];
    const float* whh = (const float*)d_in[2];
    const float* bih = (const float*)d_in[3];
    const float* bhh = (const float*)d_in[4];
    float* out = (float*)d_out;

    cudaFuncSetAttribute(lstm_fused_kernel,
                         cudaFuncAttributeMaxDynamicSharedMemorySize, SMEM_BYTES);

    prep_kernel<<<(8*2*64*8*32 + 255)/256, 256>>>(wih, whh, bih, bhh);
    lstm_fused_kernel<<<NCTAS, NTHREADS, SMEM_BYTES>>>(x, out);
}